// round 1
// baseline (speedup 1.0000x reference)
#include <cuda_runtime.h>

// Beam_Search_Tree: P[b, 64] from x[b,128] and theta0..theta4.
// Formulated as one real GEMM  Y[B,252] = X[B,128] x W'[128,252]
// (W' assembled on device each call) + per-row softmax-tree epilogue.

#define NANT    64
#define KT      128      // GEMM K  (= 2*NANT)
#define NT      256      // GEMM N  (252 used, padded)
#define MT      128      // rows per CTA
#define NBATCH  131072
#define THREADS 512

#define SY_STRIDE 258    // 64-row y staging, stride keeps float2 aligned, 2-way max conflict
#define SP_STRIDE 65     // tree scratch, odd stride -> conflict-free per-row access
#define SMEM_FLOATS (KT*NT + 64*SY_STRIDE + 64*SP_STRIDE)
#define SMEM_BYTES  (SMEM_FLOATS * 4)    // 213760 B

typedef unsigned long long u64;

// Assembled weight matrix: rows k=0..63 -> Re h coeffs, 64..127 -> Im h coeffs.
// cols 0..125: y_re per beam, cols 128..253: y_im per beam. 126/127/254/255 zero.
__device__ float g_W[KT * NT];

// ---------------------------------------------------------------------------
// Prep: build W' from thetas (node layers) + analytic DFT codebook (leaf).
// Beam order j: layer l occupies [2^(l+1)-2, 2^(l+2)-2), leaf at 62..125.
// ---------------------------------------------------------------------------
__global__ void prep_kernel(const float* __restrict__ t0, const float* __restrict__ t1,
                            const float* __restrict__ t2, const float* __restrict__ t3,
                            const float* __restrict__ t4) {
    int idx = blockIdx.x * blockDim.x + threadIdx.x;
    if (idx >= NANT * 128) return;
    int a = idx >> 7;     // antenna 0..63
    int j = idx & 127;    // padded beam 0..127
    float wr = 0.0f, wi = 0.0f;
    if (j < 62) {
        const float* th; int rel;
        if (j < 2)       { th = t0; rel = j; }
        else if (j < 6)  { th = t1; rel = j - 2; }
        else if (j < 14) { th = t2; rel = j - 6; }
        else if (j < 30) { th = t3; rel = j - 14; }
        else             { th = t4; rel = j - 30; }
        int node = rel >> 1, child = rel & 1;
        float theta = th[(node * NANT + a) * 2 + child];
        float s, c;
        sincosf(theta, &s, &c);
        wr = c * 0.125f;  wi = s * 0.125f;
    } else if (j < 126) {
        // Leaf DFT: cos(az_j) = linspace(cos 0, cos(pi-1e-6), 64)[jj]; phase = pi*a*c_j.
        // Double precision to match numpy float64 reference construction.
        int jj = j - 62;
        double cmin = cos(3.14159265358979323846 - 1e-6);
        double cj   = 1.0 + (double)jj * ((cmin - 1.0) / 63.0);
        double ph   = 3.14159265358979323846 * (double)a * cj;
        double s, c;
        sincos(ph, &s, &c);
        wr = (float)(c * 0.125);  wi = (float)(s * 0.125);
    }
    g_W[a * NT + j]              =  wr;   // y_re <- Re(h)*wr
    g_W[a * NT + 128 + j]        =  wi;   // y_im <- Re(h)*wi
    g_W[(NANT + a) * NT + j]     = -wi;   // y_re <- Im(h)*(-wi)
    g_W[(NANT + a) * NT + 128+j] =  wr;   // y_im <- Im(h)*wr
}

// ---------------------------------------------------------------------------
// Packed fp32x2 helpers (Blackwell FFMA2: 2x fp32 FMA throughput)
// ---------------------------------------------------------------------------
__device__ __forceinline__ u64 pack2(float x) {
    u64 r; asm("mov.b64 %0, {%1, %1};" : "=l"(r) : "f"(x)); return r;
}
__device__ __forceinline__ u64 packf2(float x, float y) {
    u64 r; asm("mov.b64 %0, {%1, %2};" : "=l"(r) : "f"(x), "f"(y)); return r;
}
__device__ __forceinline__ u64 ffma2(u64 a, u64 b, u64 c) {
    u64 d; asm("fma.rn.f32x2 %0, %1, %2, %3;" : "=l"(d) : "l"(a), "l"(b), "l"(c)); return d;
}
__device__ __forceinline__ float2 unpack2(u64 v) {
    float2 f; asm("mov.b64 {%0, %1}, %2;" : "=f"(f.x), "=f"(f.y) : "l"(v)); return f;
}

// ---------------------------------------------------------------------------
// Main: per CTA — 128x256x128 GEMM (8x8 reg tiles, f32x2) + tree epilogue.
// ---------------------------------------------------------------------------
__global__ __launch_bounds__(THREADS, 1)
void beam_kernel(const float* __restrict__ x, float* __restrict__ out) {
    extern __shared__ float smem[];
    float* sW = smem;                              // [128][256]
    float* sX = smem + KT * NT;                    // [128][128]   (GEMM phase)
    float* sY = smem + KT * NT;                    // [64][258]    (epilogue, aliases sX)
    float* sP = smem + KT * NT + 64 * SY_STRIDE;   // [64][65]     (tree scratch)

    const int  tid     = threadIdx.x;
    const long rowbase = (long)blockIdx.x * MT;

    // Stage W' (from L2-resident global) and the X tile (full rows -> pure linear copy).
    {
        float4*       dw = (float4*)sW;
        const float4* gw = (const float4*)g_W;
        #pragma unroll 4
        for (int i = tid; i < KT * NT / 4; i += THREADS) dw[i] = gw[i];
        float4*       dx = (float4*)sX;
        const float4* gx = (const float4*)(x + rowbase * KT);
        #pragma unroll 4
        for (int i = tid; i < MT * KT / 4; i += THREADS) dx[i] = gx[i];
    }
    __syncthreads();

    const int rg = tid >> 5;        // 0..15 : row group (8 rows)
    const int cg = tid & 31;        // 0..31 : col group (8 cols)
    const float* xa = sX + rg * 8 * KT;   // broadcast reads within warp
    const float* wb = sW + cg * 8;

    u64 acc[8][4];
    #pragma unroll
    for (int i = 0; i < 8; i++)
        #pragma unroll
        for (int jj = 0; jj < 4; jj++) acc[i][jj] = 0ull;

    #pragma unroll 4
    for (int k = 0; k < KT; k++) {
        float4 b0 = *(const float4*)(wb + k * NT);
        float4 b1 = *(const float4*)(wb + k * NT + 4);
        u64 bb0 = packf2(b0.x, b0.y), bb1 = packf2(b0.z, b0.w);
        u64 bb2 = packf2(b1.x, b1.y), bb3 = packf2(b1.z, b1.w);
        #pragma unroll
        for (int i = 0; i < 8; i++) {
            u64 av = pack2(xa[i * KT + k]);
            acc[i][0] = ffma2(av, bb0, acc[i][0]);
            acc[i][1] = ffma2(av, bb1, acc[i][1]);
            acc[i][2] = ffma2(av, bb2, acc[i][2]);
            acc[i][3] = ffma2(av, bb3, acc[i][3]);
        }
    }

    // Epilogue in two 64-row passes (sY aliases sX; barrier-protected).
    for (int pass = 0; pass < 2; pass++) {
        __syncthreads();   // GEMM reads of sX done (pass 0) / out-copy done (pass 1)
        if ((rg >> 3) == pass) {
            int rl = (rg & 7) * 8;
            #pragma unroll
            for (int i = 0; i < 8; i++) {
                float2* dst = (float2*)(sY + (rl + i) * SY_STRIDE + cg * 8);
                #pragma unroll
                for (int jj = 0; jj < 4; jj++) dst[jj] = unpack2(acc[i][jj]);
            }
        }
        __syncthreads();

        if (tid < 64) {
            // One thread per row: gains -> pairwise softmax -> 6-level tree product.
            const float* y   = sY + tid * SY_STRIDE;   // [0..125]=re, [128..253]=im
            float*       row = sP + tid * SP_STRIDE;
            row[0] = 1.0f;
            int qbase = 0, width = 1;
            for (int l = 0; l < 6; l++) {
                for (int n = width - 1; n >= 0; n--) {   // backwards: in-place expand
                    int   q  = qbase + n;
                    float r0 = y[2 * q],     i0 = y[128 + 2 * q];
                    float r1 = y[2 * q + 1], i1 = y[128 + 2 * q + 1];
                    float g0 = r0 * r0 + i0 * i0;
                    float g1 = r1 * r1 + i1 * i1;
                    float p0 = 1.0f / (1.0f + __expf(g1 - g0));  // softmax over pair
                    float c  = row[n];
                    row[2 * n]     = c * p0;
                    row[2 * n + 1] = c * (1.0f - p0);
                }
                qbase += width;
                width <<= 1;
            }
        }
        __syncthreads();

        // Coalesced write-out of this pass's 64 rows x 64 probs.
        {
            float* dst = out + (rowbase + (long)pass * 64) * 64;
            #pragma unroll 2
            for (int e = tid; e < 64 * 64; e += THREADS)
                dst[e] = sP[(e >> 6) * SP_STRIDE + (e & 63)];
        }
    }
}

// ---------------------------------------------------------------------------
extern "C" void kernel_launch(void* const* d_in, const int* in_sizes, int n_in,
                              void* d_out, int out_size) {
    const float* x  = (const float*)d_in[0];
    const float* t0 = (const float*)d_in[1];
    const float* t1 = (const float*)d_in[2];
    const float* t2 = (const float*)d_in[3];
    const float* t3 = (const float*)d_in[4];
    const float* t4 = (const float*)d_in[5];
    float* out = (float*)d_out;

    prep_kernel<<<32, 256>>>(t0, t1, t2, t3, t4);

    cudaFuncSetAttribute(beam_kernel, cudaFuncAttributeMaxDynamicSharedMemorySize, SMEM_BYTES);
    beam_kernel<<<NBATCH / MT, THREADS, SMEM_BYTES>>>(x, out);
}

// round 3
// speedup vs baseline: 2.0968x; 2.0968x over previous
#include <cuda_runtime.h>
#include <cuda_bf16.h>
#include <cstdint>

// ===========================================================================
// Beam search tree as one bf16 GEMM on mma.sync (fallback HMMA, sm_103-safe):
//   Y[B,256] = X[B,128] x W'[256,128]^T,  W' cols interleaved (re_j, im_j).
// 3-term hi/lo bf16 split (xhi*whi + xhi*wlo + xlo*whi) for fp32-grade accuracy.
// Persistent CTAs; W' staged in smem once; register gains -> smem-transposed
// gains -> per-row register softmax-tree epilogue.
// ===========================================================================

#define GRID    152
#define NTILES  1024            // 131072 rows / 128
#define THREADS 512

#define OFF_XHI 0               // X hi  [128][128] bf16, 256B rows, swizzled (32KB)
#define OFF_XLO 32768           // X lo  (32KB)          -- both alias gains later
#define OFF_WHI 65536           // W hi  [256][128] bf16 (64KB)
#define OFF_WLO 131072          // W lo  (64KB)
#define SMEM_TOTAL 196608       // 192KB

typedef unsigned long long u64;

// 256B-row swizzle: XOR 16B-chunk index with (row & 7)
__device__ __host__ __forceinline__ int swz256(int a) { return a ^ ((a >> 4) & 0x70); }

__device__ __forceinline__ uint32_t smem_u32(const void* p) {
    uint32_t a;
    asm("{ .reg .u64 t; cvta.to.shared.u64 t, %1; cvt.u32.u64 %0, t; }" : "=r"(a) : "l"(p));
    return a;
}
#define LDSM4(r, a) \
    asm volatile("ldmatrix.sync.aligned.m8n8.x4.shared.b16 {%0,%1,%2,%3}, [%4];" \
        : "=r"((r)[0]), "=r"((r)[1]), "=r"((r)[2]), "=r"((r)[3]) : "r"(a))

__device__ __forceinline__ void mma_bf16(float* d, const uint32_t* a, uint32_t b0, uint32_t b1) {
    asm volatile("mma.sync.aligned.m16n8k16.row.col.f32.bf16.bf16.f32 "
        "{%0,%1,%2,%3}, {%4,%5,%6,%7}, {%8,%9}, {%0,%1,%2,%3};"
        : "+f"(d[0]), "+f"(d[1]), "+f"(d[2]), "+f"(d[3])
        : "r"(a[0]), "r"(a[1]), "r"(a[2]), "r"(a[3]), "r"(b0), "r"(b1));
}

// ---------------------------------------------------------------------------
// Prep: W' bf16 hi/lo images in final smem layout.
// Row n of W': n=2j -> re coeffs of beam j ([wr | -wi]); n=2j+1 -> im ([wi | wr]).
// u16 index = swz256(n*256 + 2k) >> 1.
// ---------------------------------------------------------------------------
__device__ __align__(16) unsigned short g_Whi[32768];
__device__ __align__(16) unsigned short g_Wlo[32768];

__device__ __forceinline__ void store_w(int n, int k, float v) {
    __nv_bfloat16 h = __float2bfloat16(v);
    float l = v - __bfloat162float(h);
    int o = swz256(n * 256 + 2 * k) >> 1;
    g_Whi[o] = __bfloat16_as_ushort(h);
    g_Wlo[o] = __bfloat16_as_ushort(__float2bfloat16(l));
}

__global__ void prep_kernel(const float* __restrict__ t0, const float* __restrict__ t1,
                            const float* __restrict__ t2, const float* __restrict__ t3,
                            const float* __restrict__ t4) {
    int idx = blockIdx.x * blockDim.x + threadIdx.x;
    if (idx >= 64 * 128) return;
    int a = idx >> 7;      // antenna 0..63
    int j = idx & 127;     // padded beam 0..127
    float wr = 0.0f, wi = 0.0f;
    if (j < 62) {
        const float* th; int rel;
        if (j < 2)       { th = t0; rel = j; }
        else if (j < 6)  { th = t1; rel = j - 2; }
        else if (j < 14) { th = t2; rel = j - 6; }
        else if (j < 30) { th = t3; rel = j - 14; }
        else             { th = t4; rel = j - 30; }
        int node = rel >> 1, child = rel & 1;
        float theta = th[(node * 64 + a) * 2 + child];
        float s, c;
        sincosf(theta, &s, &c);
        wr = c * 0.125f;  wi = s * 0.125f;
    } else if (j < 126) {
        // DFT leaf, double precision to match numpy reference construction
        int jj = j - 62;
        double cmin = cos(3.14159265358979323846 - 1e-6);
        double cj   = 1.0 + (double)jj * ((cmin - 1.0) / 63.0);
        double ph   = 3.14159265358979323846 * (double)a * cj;
        double s, c;
        sincos(ph, &s, &c);
        wr = (float)(c * 0.125);  wi = (float)(s * 0.125);
    }
    store_w(2 * j,     a,      wr);
    store_w(2 * j,     64 + a, -wi);
    store_w(2 * j + 1, a,      wi);
    store_w(2 * j + 1, 64 + a, wr);
}

// ---------------------------------------------------------------------------
// Main persistent kernel
// ---------------------------------------------------------------------------
__global__ void __launch_bounds__(THREADS, 1)
beam_kernel(const float* __restrict__ x, float* __restrict__ out) {
    extern __shared__ char smem[];
    const uint32_t sb = smem_u32(smem);
    const int tid  = threadIdx.x;
    const int lane = tid & 31;
    const int wid  = tid >> 5;
    const int bid  = blockIdx.x;

    // ---- Prologue: stage W hi/lo images (128KB) ----
    {
        float4*       d1 = (float4*)(smem + OFF_WHI);
        const float4* s1 = (const float4*)g_Whi;
        #pragma unroll
        for (int i = tid; i < 4096; i += THREADS) d1[i] = s1[i];
        float4*       d2 = (float4*)(smem + OFF_WLO);
        const float4* s2 = (const float4*)g_Wlo;
        #pragma unroll
        for (int i = tid; i < 4096; i += THREADS) d2[i] = s2[i];
    }

    // Warp tiling: 16 warps = 4(M) x 4(N); warp tile 32 x 64.
    const int mwarp = wid >> 2, nwarp = wid & 3;
    const int m0 = mwarp * 32, n0 = nwarp * 64;
    const int lrow  = lane & 15;
    const int kh2   = (lane >> 4) * 16;   // byte offset of k-half (8 elems * 2B)
    const int tig   = lane & 3, gid = lane >> 2;

    // Per-lane ldmatrix address components (swizzle mask = (row&7)<<4, k-independent)
    uint32_t baseA[2], xmA[2], baseBh[4], baseBl[4], xmB[4];
    #pragma unroll
    for (int mb = 0; mb < 2; mb++) {
        int r = m0 + mb * 16 + lrow;
        baseA[mb] = sb + OFF_XHI + (r << 8);
        xmA[mb]   = (r & 7) << 4;
    }
    #pragma unroll
    for (int np = 0; np < 4; np++) {
        int r = n0 + np * 16 + lrow;
        baseBh[np] = sb + OFF_WHI + (r << 8);
        baseBl[np] = sb + OFF_WLO + (r << 8);
        xmB[np]    = (r & 7) << 4;
    }

    const int n_it = (NTILES - 1 - bid) / GRID + 1;

    for (int it = 0; it < n_it; it++) {
        const long tile = bid + (long)it * GRID;
        __syncthreads();   // gains region (X smem) free for reuse

        // ---- Load X tile: fp32 [128][128] -> bf16 hi/lo swizzled smem ----
        {
            const float4* gx = (const float4*)(x + tile * 16384);
            #pragma unroll
            for (int i = 0; i < 8; i++) {
                int i4 = tid + THREADS * i;        // 0..4095
                float4 v = gx[i4];
                int row = i4 >> 5, c = i4 & 31;
                int boff = swz256(row * 256 + c * 8);
                __nv_bfloat16 h0 = __float2bfloat16(v.x), h1 = __float2bfloat16(v.y);
                __nv_bfloat16 h2 = __float2bfloat16(v.z), h3 = __float2bfloat16(v.w);
                u64 hi = (u64)__bfloat16_as_ushort(h0)
                       | ((u64)__bfloat16_as_ushort(h1) << 16)
                       | ((u64)__bfloat16_as_ushort(h2) << 32)
                       | ((u64)__bfloat16_as_ushort(h3) << 48);
                u64 lo = (u64)__bfloat16_as_ushort(__float2bfloat16(v.x - __bfloat162float(h0)))
                       | ((u64)__bfloat16_as_ushort(__float2bfloat16(v.y - __bfloat162float(h1))) << 16)
                       | ((u64)__bfloat16_as_ushort(__float2bfloat16(v.z - __bfloat162float(h2))) << 32)
                       | ((u64)__bfloat16_as_ushort(__float2bfloat16(v.w - __bfloat162float(h3))) << 48);
                *(u64*)(smem + OFF_XHI + boff) = hi;
                *(u64*)(smem + OFF_XLO + boff) = lo;
            }
        }
        __syncthreads();

        // ---- GEMM: 8 k-steps, 3-term split ----
        float acc[2][8][4];
        #pragma unroll
        for (int mb = 0; mb < 2; mb++)
            #pragma unroll
            for (int nb = 0; nb < 8; nb++)
                #pragma unroll
                for (int c = 0; c < 4; c++) acc[mb][nb][c] = 0.0f;

        #pragma unroll
        for (int s = 0; s < 8; s++) {
            const int k2 = 32 * s + kh2;           // byte offset of this lane's k
            uint32_t ah[2][4], al[2][4], bb[4][4];
            #pragma unroll
            for (int mb = 0; mb < 2; mb++) {
                LDSM4(ah[mb], baseA[mb] + (k2 ^ xmA[mb]));
                LDSM4(al[mb], baseA[mb] + 32768 + (k2 ^ xmA[mb]));
            }
            #pragma unroll
            for (int np = 0; np < 4; np++) LDSM4(bb[np], baseBh[np] + (k2 ^ xmB[np]));
            // term1: xhi*whi, term3: xlo*whi
            #pragma unroll
            for (int mb = 0; mb < 2; mb++)
                #pragma unroll
                for (int np = 0; np < 4; np++) {
                    mma_bf16(acc[mb][2*np],   ah[mb], bb[np][0], bb[np][2]);
                    mma_bf16(acc[mb][2*np+1], ah[mb], bb[np][1], bb[np][3]);
                    mma_bf16(acc[mb][2*np],   al[mb], bb[np][0], bb[np][2]);
                    mma_bf16(acc[mb][2*np+1], al[mb], bb[np][1], bb[np][3]);
                }
            // term2: xhi*wlo
            #pragma unroll
            for (int np = 0; np < 4; np++) LDSM4(bb[np], baseBl[np] + (k2 ^ xmB[np]));
            #pragma unroll
            for (int mb = 0; mb < 2; mb++)
                #pragma unroll
                for (int np = 0; np < 4; np++) {
                    mma_bf16(acc[mb][2*np],   ah[mb], bb[np][0], bb[np][2]);
                    mma_bf16(acc[mb][2*np+1], ah[mb], bb[np][1], bb[np][3]);
                }
        }
        __syncthreads();   // all warps done reading X smem

        // ---- Gains -> transposed smem [beam j][row m], XOR pad (j&3)<<3 ----
        {
            float* gains = (float*)smem;
            #pragma unroll
            for (int mb = 0; mb < 2; mb++)
                #pragma unroll
                for (int nb = 0; nb < 8; nb++) {
                    int j = nwarp * 32 + nb * 4 + tig;       // beam
                    int m = m0 + mb * 16 + gid;              // row
                    int xm = (j & 3) << 3;
                    float g0 = acc[mb][nb][0] * acc[mb][nb][0] + acc[mb][nb][1] * acc[mb][nb][1];
                    float g1 = acc[mb][nb][2] * acc[mb][nb][2] + acc[mb][nb][3] * acc[mb][nb][3];
                    gains[j * 128 + (m ^ xm)]       = g0;
                    gains[j * 128 + ((m + 8) ^ xm)] = g1;
                }
        }
        __syncthreads();

        // ---- Tree epilogue: one thread per row (threads 0..127) ----
        if (tid < 128) {
            const float* gains = (const float*)smem;
            const int t = tid;
            float rowp[64];
            rowp[0] = 1.0f;
            int qbase = 0, width = 1;
            #pragma unroll
            for (int l = 0; l < 6; l++) {
                #pragma unroll 32
                for (int n = width - 1; n >= 0; n--) {
                    int   q  = qbase + n;
                    int   j0 = 2 * q, j1 = 2 * q + 1;
                    float g0 = gains[j0 * 128 + (t ^ ((j0 & 3) << 3))];
                    float g1 = gains[j1 * 128 + (t ^ ((j1 & 3) << 3))];
                    float p0 = 1.0f / (1.0f + __expf(g1 - g0));
                    float pp = rowp[n];
                    rowp[2 * n]     = pp * p0;
                    rowp[2 * n + 1] = pp - pp * p0;
                }
                qbase += width;
                width <<= 1;
            }
            float4* o4 = (float4*)(out + (tile * 128 + t) * 64);
            #pragma unroll
            for (int jj = 0; jj < 16; jj++)
                o4[jj] = make_float4(rowp[4*jj], rowp[4*jj+1], rowp[4*jj+2], rowp[4*jj+3]);
        }
    }
}

// ---------------------------------------------------------------------------
extern "C" void kernel_launch(void* const* d_in, const int* in_sizes, int n_in,
                              void* d_out, int out_size) {
    const float* x  = (const float*)d_in[0];
    const float* t0 = (const float*)d_in[1];
    const float* t1 = (const float*)d_in[2];
    const float* t2 = (const float*)d_in[3];
    const float* t3 = (const float*)d_in[4];
    const float* t4 = (const float*)d_in[5];
    float* out = (float*)d_out;

    prep_kernel<<<32, 256>>>(t0, t1, t2, t3, t4);

    cudaFuncSetAttribute(beam_kernel, cudaFuncAttributeMaxDynamicSharedMemorySize, SMEM_TOTAL);
    beam_kernel<<<GRID, THREADS, SMEM_TOTAL>>>(x, out);
}